// round 3
// baseline (speedup 1.0000x reference)
#include <cuda_runtime.h>
#include <math.h>

#define THW 65536
#define C_ 32
#define KNN 8

// Scratch (allowed: __device__ globals, no allocation)
__device__ float g_stacked[256 * THW];   // 64 MB: [k*C+c][THW]
__device__ float g_x[C_ * THW];          // 8 MB : conv output [C][THW]

// ---------------------------------------------------------------------------
// Stage 1: non-local kNN search + softmax-weighted stacking
// One thread per voxel. vid layout [C][T][H][W] flat = c*65536 + p.
// ---------------------------------------------------------------------------
__global__ __launch_bounds__(128) void nl_stack_kernel(const float* __restrict__ vid) {
    int p = blockIdx.x * 128 + threadIdx.x;
    int t = p >> 14;
    int h = (p >> 7) & 127;
    int w = p & 127;

    float x[C_];
#pragma unroll
    for (int c = 0; c < C_; c++) x[c] = vid[c * THW + p];

    float bd[KNN];
    int   bq[KNN];
#pragma unroll
    for (int k = 0; k < KNN; k++) { bd[k] = 3.4e38f; bq[k] = 0; }

    // Offset order matches jax meshgrid(dts, dss, dss, 'ij') flattening:
    // dt outer, dh middle, dw inner, all ascending -> stable tie-break matches top_k.
    for (int dt = -1; dt <= 1; dt++) {
        int ti = t + dt; ti = ti < 0 ? 0 : (ti > 3 ? 3 : ti);
        for (int dh = -4; dh <= 4; dh++) {
            int hi = h + dh; hi = hi < 0 ? 0 : (hi > 127 ? 127 : hi);
            for (int dw = -4; dw <= 4; dw++) {
                int wi = w + dw; wi = wi < 0 ? 0 : (wi > 127 ? 127 : wi);
                int q = ti * 16384 + hi * 128 + wi;
                float d = 0.0f;
#pragma unroll
                for (int c = 0; c < C_; c++) {
                    float df = x[c] - vid[c * THW + q];
                    d = fmaf(df, df, d);
                }
                if (d < bd[KNN - 1]) {
                    // bd sorted ascending; shift strictly-greater entries up.
                    int ins = KNN - 1;
#pragma unroll
                    for (int i = KNN - 2; i >= 0; i--) {
                        if (d < bd[i]) { bd[i + 1] = bd[i]; bq[i + 1] = bq[i]; ins = i; }
                    }
                    bd[ins] = d; bq[ins] = q;
                }
            }
        }
    }

    // softmax(-dist) with max subtraction (max of -d is -bd[0])
    float e[KNN], s = 0.0f;
#pragma unroll
    for (int k = 0; k < KNN; k++) { e[k] = __expf(bd[0] - bd[k]); s += e[k]; }
    float inv = 1.0f / s;

#pragma unroll
    for (int k = 0; k < KNN; k++) {
        float wk = e[k] * inv;
        int q = bq[k];
#pragma unroll
        for (int c = 0; c < C_; c++) {
            g_stacked[(k * C_ + c) * THW + p] = vid[c * THW + q] * wk;
        }
    }
}

// ---------------------------------------------------------------------------
// Stage 2: conv3d (1,3,3), 256 -> 32 channels, pad (1,1) spatial.
// One thread per voxel, all 32 output channels in registers.
// Weight tap slice [256][32] staged in smem per tap.
// Branchless padding: clamped address + zero mask (SEL hides in FFMA gaps).
// ---------------------------------------------------------------------------
__global__ __launch_bounds__(128) void conv_kernel(const float* __restrict__ cw,
                                                   const float* __restrict__ cb) {
    __shared__ float sw[256 * C_];   // 32 KB
    int tid = threadIdx.x;
    int p = blockIdx.x * 128 + tid;
    int t = p >> 14;
    int h = (p >> 7) & 127;
    int w = p & 127;

    float acc[C_];
#pragma unroll
    for (int o = 0; o < C_; o++) acc[o] = cb[o];

    for (int tap = 0; tap < 9; tap++) {
        int kh = tap / 3 - 1;
        int kw = tap % 3 - 1;
        __syncthreads();
        // cw layout (O=32, IC=256, 1, 3, 3): flat = (o*256+ic)*9 + tap
        for (int idx = tid; idx < 256 * C_; idx += 128) {
            int ic = idx >> 5, o = idx & 31;
            sw[idx] = cw[(o * 256 + ic) * 9 + tap];
        }
        __syncthreads();
        int hh = h + kh, ww = w + kw;
        bool valid = (hh >= 0) & (hh < 128) & (ww >= 0) & (ww < 128);
        // clamp so the address is always legal; mask kills OOB contribution
        int hc = hh < 0 ? 0 : (hh > 127 ? 127 : hh);
        int wc = ww < 0 ? 0 : (ww > 127 ? 127 : ww);
        float mask = valid ? 1.0f : 0.0f;
        int base = t * 16384 + hc * 128 + wc;
#pragma unroll 4
        for (int ic = 0; ic < 256; ic++) {
            float xv = g_stacked[ic * THW + base] * mask;
            const float* wr = &sw[ic * C_];
#pragma unroll
            for (int o = 0; o < C_; o++) acc[o] = fmaf(xv, wr[o], acc[o]);
        }
    }
#pragma unroll
    for (int o = 0; o < C_; o++) g_x[o * THW + p] = acc[o];
}

// ---------------------------------------------------------------------------
// Stage 3: 2 transformer blocks on 8x8 windows, fused with final vid + out.
// 128 threads = 2 windows x 64 tokens. Token state in registers, K/V in smem.
// ---------------------------------------------------------------------------
__device__ __forceinline__ float gelu_tanh(float a) {
    float inner = 0.7978845608028654f * fmaf(0.044715f * a, a * a, a);
    return 0.5f * a * (1.0f + tanhf(inner));
}

__global__ __launch_bounds__(128) void xf_kernel(
    const float* __restrict__ vid, float* __restrict__ out,
    const float* __restrict__ ln1_g, const float* __restrict__ ln1_b,
    const float* __restrict__ qkv_w, const float* __restrict__ qkv_b,
    const float* __restrict__ proj_w, const float* __restrict__ proj_b,
    const float* __restrict__ ln2_g, const float* __restrict__ ln2_b,
    const float* __restrict__ fc1_w, const float* __restrict__ fc1_b,
    const float* __restrict__ fc2_w, const float* __restrict__ fc2_b)
{
    extern __shared__ float sm[];
    float* s_qkvw = sm;                  // 3072
    float* s_qkvb = s_qkvw + 3072;       // 96
    float* s_projw = s_qkvb + 96;        // 1024
    float* s_projb = s_projw + 1024;     // 32
    float* s_fc1w = s_projb + 32;        // 2048
    float* s_fc1b = s_fc1w + 2048;       // 64
    float* s_fc2w = s_fc1b + 64;         // 2048
    float* s_fc2b = s_fc2w + 2048;       // 32
    float* s_g1 = s_fc2b + 32;           // 32
    float* s_b1 = s_g1 + 32;             // 32
    float* s_g2 = s_b1 + 32;             // 32
    float* s_b2 = s_g2 + 32;             // 32
    float* s_kv = s_b2 + 32;             // 2 windows x (2 x 64 x 33)

    int tid = threadIdx.x;
    int wi = tid >> 6;      // window within block (0..1)
    int j = tid & 63;       // token within window

    float* kbuf = s_kv + wi * (2 * 64 * 33);
    float* vbuf = kbuf + 64 * 33;

    int wg = blockIdx.x * 2 + wi;                  // global window id, 0..1023
    int t = wg >> 8, nh = (wg >> 4) & 15, nw = wg & 15;
    int h = nh * 8 + (j >> 3);
    int w = nw * 8 + (j & 7);
    int p = t * 16384 + h * 128 + w;

    float xr[32];
#pragma unroll
    for (int c = 0; c < 32; c++) xr[c] = g_x[c * THW + p];

    for (int L = 0; L < 2; L++) {
        __syncthreads();   // prior layer's smem reads complete
        for (int idx = tid; idx < 3072; idx += 128) s_qkvw[idx] = qkv_w[L * 3072 + idx];
        for (int idx = tid; idx < 2048; idx += 128) {
            s_fc1w[idx] = fc1_w[L * 2048 + idx];
            s_fc2w[idx] = fc2_w[L * 2048 + idx];
        }
        for (int idx = tid; idx < 1024; idx += 128) s_projw[idx] = proj_w[L * 1024 + idx];
        if (tid < 96) s_qkvb[tid] = qkv_b[L * 96 + tid];
        if (tid < 64) s_fc1b[tid] = fc1_b[L * 64 + tid];
        if (tid < 32) {
            s_projb[tid] = proj_b[L * 32 + tid];
            s_fc2b[tid] = fc2_b[L * 32 + tid];
            s_g1[tid] = ln1_g[L * 32 + tid];
            s_b1[tid] = ln1_b[L * 32 + tid];
            s_g2[tid] = ln2_g[L * 32 + tid];
            s_b2[tid] = ln2_b[L * 32 + tid];
        }
        __syncthreads();

        // ---- LN1 ----
        float mu = 0.0f;
#pragma unroll
        for (int c = 0; c < 32; c++) mu += xr[c];
        mu *= 0.03125f;
        float var = 0.0f;
#pragma unroll
        for (int c = 0; c < 32; c++) { float d = xr[c] - mu; var = fmaf(d, d, var); }
        var *= 0.03125f;
        float rstd = rsqrtf(var + 1e-5f);
        float hv[32];
#pragma unroll
        for (int c = 0; c < 32; c++) hv[c] = (xr[c] - mu) * rstd * s_g1[c] + s_b1[c];

        // ---- QKV ----
        float q[32];
#pragma unroll
        for (int jq = 0; jq < 32; jq++) {
            float s = s_qkvb[jq];
#pragma unroll
            for (int c = 0; c < 32; c++) s = fmaf(hv[c], s_qkvw[c * 96 + jq], s);
            q[jq] = s;
        }
        for (int jk = 0; jk < 32; jk++) {
            float s = s_qkvb[32 + jk];
#pragma unroll
            for (int c = 0; c < 32; c++) s = fmaf(hv[c], s_qkvw[c * 96 + 32 + jk], s);
            kbuf[j * 33 + jk] = s;
        }
        for (int jv = 0; jv < 32; jv++) {
            float s = s_qkvb[64 + jv];
#pragma unroll
            for (int c = 0; c < 32; c++) s = fmaf(hv[c], s_qkvw[c * 96 + 64 + jv], s);
            vbuf[j * 33 + jv] = s;
        }
        __syncthreads();

        // ---- attention (4 heads, hd=8), 3-pass streaming softmax ----
        float ov[32];
#pragma unroll
        for (int c = 0; c < 32; c++) ov[c] = 0.0f;
        const float scale = 0.3535533905932738f;   // 8^-0.5
#pragma unroll
        for (int hh = 0; hh < 4; hh++) {
            const int base = hh * 8;
            float mx = -1e30f;
            for (int kk = 0; kk < 64; kk++) {
                float s = 0.0f;
#pragma unroll
                for (int d = 0; d < 8; d++) s = fmaf(q[base + d], kbuf[kk * 33 + base + d], s);
                mx = fmaxf(mx, s * scale);
            }
            float sum = 0.0f;
            for (int kk = 0; kk < 64; kk++) {
                float s = 0.0f;
#pragma unroll
                for (int d = 0; d < 8; d++) s = fmaf(q[base + d], kbuf[kk * 33 + base + d], s);
                sum += __expf(s * scale - mx);
            }
            float inv = 1.0f / sum;
            for (int kk = 0; kk < 64; kk++) {
                float s = 0.0f;
#pragma unroll
                for (int d = 0; d < 8; d++) s = fmaf(q[base + d], kbuf[kk * 33 + base + d], s);
                float pw = __expf(s * scale - mx) * inv;
#pragma unroll
                for (int d = 0; d < 8; d++) ov[base + d] = fmaf(pw, vbuf[kk * 33 + base + d], ov[base + d]);
            }
        }

        // ---- proj + residual ----
#pragma unroll
        for (int c = 0; c < 32; c++) {
            float s = s_projb[c];
#pragma unroll
            for (int u = 0; u < 32; u++) s = fmaf(ov[u], s_projw[u * 32 + c], s);
            xr[c] += s;
        }

        // ---- LN2 ----
        mu = 0.0f;
#pragma unroll
        for (int c = 0; c < 32; c++) mu += xr[c];
        mu *= 0.03125f;
        var = 0.0f;
#pragma unroll
        for (int c = 0; c < 32; c++) { float d = xr[c] - mu; var = fmaf(d, d, var); }
        var *= 0.03125f;
        rstd = rsqrtf(var + 1e-5f);
#pragma unroll
        for (int c = 0; c < 32; c++) hv[c] = (xr[c] - mu) * rstd * s_g2[c] + s_b2[c];

        // ---- MLP: 32 -> 64 (gelu) -> 32, streaming over hidden units ----
        float acc[32];
#pragma unroll
        for (int c = 0; c < 32; c++) acc[c] = 0.0f;
        for (int u = 0; u < 64; u++) {
            float a = s_fc1b[u];
#pragma unroll
            for (int c = 0; c < 32; c++) a = fmaf(hv[c], s_fc1w[c * 64 + u], a);
            float g = gelu_tanh(a);
#pragma unroll
            for (int c = 0; c < 32; c++) acc[c] = fmaf(g, s_fc2w[u * 32 + c], acc[c]);
        }
#pragma unroll
        for (int c = 0; c < 32; c++) xr[c] += acc[c] + s_fc2b[c];
    }

    // final residual with original video
#pragma unroll
    for (int c = 0; c < 32; c++) out[c * THW + p] = vid[c * THW + p] + xr[c];
}

// ---------------------------------------------------------------------------
extern "C" void kernel_launch(void* const* d_in, const int* in_sizes, int n_in,
                              void* d_out, int out_size) {
    const float* vid    = (const float*)d_in[0];
    const float* conv_w = (const float*)d_in[1];
    const float* conv_b = (const float*)d_in[2];
    const float* ln1_g  = (const float*)d_in[3];
    const float* ln1_b  = (const float*)d_in[4];
    const float* qkv_w  = (const float*)d_in[5];
    const float* qkv_b  = (const float*)d_in[6];
    const float* proj_w = (const float*)d_in[7];
    const float* proj_b = (const float*)d_in[8];
    const float* ln2_g  = (const float*)d_in[9];
    const float* ln2_b  = (const float*)d_in[10];
    const float* fc1_w  = (const float*)d_in[11];
    const float* fc1_b  = (const float*)d_in[12];
    const float* fc2_w  = (const float*)d_in[13];
    const float* fc2_b  = (const float*)d_in[14];
    float* out = (float*)d_out;

    nl_stack_kernel<<<512, 128>>>(vid);
    conv_kernel<<<512, 128>>>(conv_w, conv_b);

    const int smem_bytes = (8544 + 2 * 2 * 64 * 33) * (int)sizeof(float);  // 67968
    cudaFuncSetAttribute(xf_kernel, cudaFuncAttributeMaxDynamicSharedMemorySize, smem_bytes);
    xf_kernel<<<512, 128, smem_bytes>>>(vid, out,
                                        ln1_g, ln1_b, qkv_w, qkv_b, proj_w, proj_b,
                                        ln2_g, ln2_b, fc1_w, fc1_b, fc2_w, fc2_b);
}

// round 5
// speedup vs baseline: 1.6977x; 1.6977x over previous
#include <cuda_runtime.h>
#include <math.h>

#define THW 65536
#define C_ 32
#define KNN 8

// Scratch (allowed: __device__ globals, no allocation)
__device__ float g_stacked[256 * THW];   // 64 MB: [k*C+c][THW]
__device__ float g_x[C_ * THW];          // 8 MB : conv output [C][THW]
__device__ float g_wT[9 * 256 * 32];     // tf32-rounded conv weights [tap][ic][o]

__device__ __forceinline__ float tf32_rna(float v) {
    unsigned u;
    asm("cvt.rna.tf32.f32 %0, %1;" : "=r"(u) : "f"(v));
    return __uint_as_float(u);
}

// ---------------------------------------------------------------------------
// Stage 1: non-local kNN search + softmax-weighted stacking
// One thread per voxel. 4 partial distance accumulators (chain depth 32 -> 8).
// ---------------------------------------------------------------------------
__global__ __launch_bounds__(128) void nl_stack_kernel(const float* __restrict__ vid) {
    int p = blockIdx.x * 128 + threadIdx.x;
    int t = p >> 14;
    int h = (p >> 7) & 127;
    int w = p & 127;

    float x[C_];
#pragma unroll
    for (int c = 0; c < C_; c++) x[c] = vid[c * THW + p];

    float bd[KNN];
    int   bq[KNN];
#pragma unroll
    for (int k = 0; k < KNN; k++) { bd[k] = 3.4e38f; bq[k] = 0; }

    // Offset order matches jax meshgrid(dts, dss, dss, 'ij') flattening.
    for (int dt = -1; dt <= 1; dt++) {
        int ti = t + dt; ti = ti < 0 ? 0 : (ti > 3 ? 3 : ti);
        for (int dh = -4; dh <= 4; dh++) {
            int hi = h + dh; hi = hi < 0 ? 0 : (hi > 127 ? 127 : hi);
            for (int dw = -4; dw <= 4; dw++) {
                int wi = w + dw; wi = wi < 0 ? 0 : (wi > 127 ? 127 : wi);
                int q = ti * 16384 + hi * 128 + wi;
                float d0 = 0.0f, d1 = 0.0f, d2 = 0.0f, d3 = 0.0f;
#pragma unroll
                for (int c = 0; c < C_; c += 4) {
                    float a0 = x[c + 0] - vid[(c + 0) * THW + q];
                    float a1 = x[c + 1] - vid[(c + 1) * THW + q];
                    float a2 = x[c + 2] - vid[(c + 2) * THW + q];
                    float a3 = x[c + 3] - vid[(c + 3) * THW + q];
                    d0 = fmaf(a0, a0, d0);
                    d1 = fmaf(a1, a1, d1);
                    d2 = fmaf(a2, a2, d2);
                    d3 = fmaf(a3, a3, d3);
                }
                float d = (d0 + d1) + (d2 + d3);
                if (d < bd[KNN - 1]) {
                    int ins = KNN - 1;
#pragma unroll
                    for (int i = KNN - 2; i >= 0; i--) {
                        if (d < bd[i]) { bd[i + 1] = bd[i]; bq[i + 1] = bq[i]; ins = i; }
                    }
                    bd[ins] = d; bq[ins] = q;
                }
            }
        }
    }

    float e[KNN], s = 0.0f;
#pragma unroll
    for (int k = 0; k < KNN; k++) { e[k] = __expf(bd[0] - bd[k]); s += e[k]; }
    float inv = 1.0f / s;

#pragma unroll
    for (int k = 0; k < KNN; k++) {
        float wk = e[k] * inv;
        int q = bq[k];
#pragma unroll
        for (int c = 0; c < C_; c++) {
            g_stacked[(k * C_ + c) * THW + p] = vid[c * THW + q] * wk;
        }
    }
}

// ---------------------------------------------------------------------------
// Weight pre-transform: cw (O=32, IC=256, 1,3,3) -> g_wT[tap][ic][o], tf32-rna.
// ---------------------------------------------------------------------------
__global__ __launch_bounds__(128) void wT_kernel(const float* __restrict__ cw) {
    int i = blockIdx.x * 128 + threadIdx.x;   // 73728 = tap*8192 + ic*32 + o
    int o = i & 31;
    int ic = (i >> 5) & 255;
    int tap = i >> 13;
    g_wT[i] = tf32_rna(cw[(o * 256 + ic) * 9 + tap]);
}

// ---------------------------------------------------------------------------
// Stage 2: conv as implicit GEMM on tf32 mma.sync.m16n8k8.
// CTA = 32 (all out ch) x 64 voxels (half a row: h,t uniform per tile).
// K = 9 taps x 256 ic, staged in 64-ic smem chunks. 4 warps, each 32x16 out.
// ---------------------------------------------------------------------------
__global__ __launch_bounds__(128) void conv_mma_kernel(const float* __restrict__ cb) {
    __shared__ float sA[64 * 40];   // [ic][o], pitch 40 -> conflict-free frags
    __shared__ float sB[64 * 72];   // [ic][n], pitch 72 -> conflict-free frags

    int tid = threadIdx.x;
    int lane = tid & 31, wid = tid >> 5;
    int lg = lane >> 2;   // 0..7
    int lk = lane & 3;    // 0..3

    int p0 = blockIdx.x * 64;
    int t = p0 >> 14, h = (p0 >> 7) & 127, wbase = p0 & 127;   // wbase in {0,64}

    float c[2][2][4];
#pragma unroll
    for (int mt = 0; mt < 2; mt++)
#pragma unroll
        for (int nt = 0; nt < 2; nt++)
#pragma unroll
            for (int r = 0; r < 4; r++) c[mt][nt][r] = 0.0f;

    for (int tap = 0; tap < 9; tap++) {
        int kh = tap / 3 - 1, kw = tap % 3 - 1;
        int hp = h + kh;
        if (hp < 0 || hp > 127) continue;          // uniform across CTA
        int base = t * 16384 + hp * 128 + wbase + kw;

        for (int ic0 = 0; ic0 < 256; ic0 += 64) {
            __syncthreads();
            // stage A: 64x32 weights (already tf32-rounded)
#pragma unroll
            for (int r = 0; r < 16; r++) {
                int idx = r * 128 + tid;
                int icl = idx >> 5, o = idx & 31;
                sA[icl * 40 + o] = g_wT[(tap * 256 + ic0 + icl) * 32 + o];
            }
            // stage B: 64x64 activations, w-edge guard + tf32 round
#pragma unroll
            for (int r = 0; r < 32; r++) {
                int idx = r * 128 + tid;
                int icl = idx >> 6, n = idx & 63;
                int wq = wbase + n + kw;
                float v = 0.0f;
                if ((unsigned)wq < 128u)
                    v = g_stacked[(ic0 + icl) * THW + base + n];
                sB[icl * 72 + n] = tf32_rna(v);
            }
            __syncthreads();

#pragma unroll
            for (int kk = 0; kk < 8; kk++) {
                int kc = kk * 8;
                unsigned a[2][4], b[2][2];
#pragma unroll
                for (int mt = 0; mt < 2; mt++) {
                    int ob = mt * 16;
                    a[mt][0] = __float_as_uint(sA[(kc + lk) * 40 + ob + lg]);
                    a[mt][1] = __float_as_uint(sA[(kc + lk) * 40 + ob + lg + 8]);
                    a[mt][2] = __float_as_uint(sA[(kc + 4 + lk) * 40 + ob + lg]);
                    a[mt][3] = __float_as_uint(sA[(kc + 4 + lk) * 40 + ob + lg + 8]);
                }
#pragma unroll
                for (int nt = 0; nt < 2; nt++) {
                    int n0 = wid * 16 + nt * 8;
                    b[nt][0] = __float_as_uint(sB[(kc + lk) * 72 + n0 + lg]);
                    b[nt][1] = __float_as_uint(sB[(kc + 4 + lk) * 72 + n0 + lg]);
                }
#pragma unroll
                for (int mt = 0; mt < 2; mt++)
#pragma unroll
                    for (int nt = 0; nt < 2; nt++) {
                        asm volatile(
                            "mma.sync.aligned.m16n8k8.row.col.f32.tf32.tf32.f32 "
                            "{%0,%1,%2,%3}, {%4,%5,%6,%7}, {%8,%9}, {%0,%1,%2,%3};"
                            : "+f"(c[mt][nt][0]), "+f"(c[mt][nt][1]),
                              "+f"(c[mt][nt][2]), "+f"(c[mt][nt][3])
                            : "r"(a[mt][0]), "r"(a[mt][1]), "r"(a[mt][2]), "r"(a[mt][3]),
                              "r"(b[nt][0]), "r"(b[nt][1]));
                    }
            }
        }
    }

    // epilogue: D[m][n] -> g_x[m*THW + p0+n], + bias
#pragma unroll
    for (int mt = 0; mt < 2; mt++) {
        int r0 = mt * 16 + lg;
        float b0 = cb[r0], b1 = cb[r0 + 8];
#pragma unroll
        for (int nt = 0; nt < 2; nt++) {
            int col = wid * 16 + nt * 8 + 2 * lk;
            float2 v0 = make_float2(c[mt][nt][0] + b0, c[mt][nt][1] + b0);
            float2 v1 = make_float2(c[mt][nt][2] + b1, c[mt][nt][3] + b1);
            *(float2*)&g_x[r0 * THW + p0 + col] = v0;
            *(float2*)&g_x[(r0 + 8) * THW + p0 + col] = v1;
        }
    }
}

// ---------------------------------------------------------------------------
// Stage 3: 2 transformer blocks on 8x8 windows, fused with final vid + out.
// (unchanged from the passing round-3 kernel)
// ---------------------------------------------------------------------------
__device__ __forceinline__ float gelu_tanh(float a) {
    float inner = 0.7978845608028654f * fmaf(0.044715f * a, a * a, a);
    return 0.5f * a * (1.0f + tanhf(inner));
}

__global__ __launch_bounds__(128) void xf_kernel(
    const float* __restrict__ vid, float* __restrict__ out,
    const float* __restrict__ ln1_g, const float* __restrict__ ln1_b,
    const float* __restrict__ qkv_w, const float* __restrict__ qkv_b,
    const float* __restrict__ proj_w, const float* __restrict__ proj_b,
    const float* __restrict__ ln2_g, const float* __restrict__ ln2_b,
    const float* __restrict__ fc1_w, const float* __restrict__ fc1_b,
    const float* __restrict__ fc2_w, const float* __restrict__ fc2_b)
{
    extern __shared__ float sm[];
    float* s_qkvw = sm;                  // 3072
    float* s_qkvb = s_qkvw + 3072;       // 96
    float* s_projw = s_qkvb + 96;        // 1024
    float* s_projb = s_projw + 1024;     // 32
    float* s_fc1w = s_projb + 32;        // 2048
    float* s_fc1b = s_fc1w + 2048;       // 64
    float* s_fc2w = s_fc1b + 64;         // 2048
    float* s_fc2b = s_fc2w + 2048;       // 32
    float* s_g1 = s_fc2b + 32;           // 32
    float* s_b1 = s_g1 + 32;             // 32
    float* s_g2 = s_b1 + 32;             // 32
    float* s_b2 = s_g2 + 32;             // 32
    float* s_kv = s_b2 + 32;             // 2 windows x (2 x 64 x 33)

    int tid = threadIdx.x;
    int wi = tid >> 6;
    int j = tid & 63;

    float* kbuf = s_kv + wi * (2 * 64 * 33);
    float* vbuf = kbuf + 64 * 33;

    int wg = blockIdx.x * 2 + wi;
    int t = wg >> 8, nh = (wg >> 4) & 15, nw = wg & 15;
    int h = nh * 8 + (j >> 3);
    int w = nw * 8 + (j & 7);
    int p = t * 16384 + h * 128 + w;

    float xr[32];
#pragma unroll
    for (int c = 0; c < 32; c++) xr[c] = g_x[c * THW + p];

    for (int L = 0; L < 2; L++) {
        __syncthreads();
        for (int idx = tid; idx < 3072; idx += 128) s_qkvw[idx] = qkv_w[L * 3072 + idx];
        for (int idx = tid; idx < 2048; idx += 128) {
            s_fc1w[idx] = fc1_w[L * 2048 + idx];
            s_fc2w[idx] = fc2_w[L * 2048 + idx];
        }
        for (int idx = tid; idx < 1024; idx += 128) s_projw[idx] = proj_w[L * 1024 + idx];
        if (tid < 96) s_qkvb[tid] = qkv_b[L * 96 + tid];
        if (tid < 64) s_fc1b[tid] = fc1_b[L * 64 + tid];
        if (tid < 32) {
            s_projb[tid] = proj_b[L * 32 + tid];
            s_fc2b[tid] = fc2_b[L * 32 + tid];
            s_g1[tid] = ln1_g[L * 32 + tid];
            s_b1[tid] = ln1_b[L * 32 + tid];
            s_g2[tid] = ln2_g[L * 32 + tid];
            s_b2[tid] = ln2_b[L * 32 + tid];
        }
        __syncthreads();

        float mu = 0.0f;
#pragma unroll
        for (int c = 0; c < 32; c++) mu += xr[c];
        mu *= 0.03125f;
        float var = 0.0f;
#pragma unroll
        for (int c = 0; c < 32; c++) { float d = xr[c] - mu; var = fmaf(d, d, var); }
        var *= 0.03125f;
        float rstd = rsqrtf(var + 1e-5f);
        float hv[32];
#pragma unroll
        for (int c = 0; c < 32; c++) hv[c] = (xr[c] - mu) * rstd * s_g1[c] + s_b1[c];

        float q[32];
#pragma unroll
        for (int jq = 0; jq < 32; jq++) {
            float s = s_qkvb[jq];
#pragma unroll
            for (int c = 0; c < 32; c++) s = fmaf(hv[c], s_qkvw[c * 96 + jq], s);
            q[jq] = s;
        }
        for (int jk = 0; jk < 32; jk++) {
            float s = s_qkvb[32 + jk];
#pragma unroll
            for (int c = 0; c < 32; c++) s = fmaf(hv[c], s_qkvw[c * 96 + 32 + jk], s);
            kbuf[j * 33 + jk] = s;
        }
        for (int jv = 0; jv < 32; jv++) {
            float s = s_qkvb[64 + jv];
#pragma unroll
            for (int c = 0; c < 32; c++) s = fmaf(hv[c], s_qkvw[c * 96 + 64 + jv], s);
            vbuf[j * 33 + jv] = s;
        }
        __syncthreads();

        float ov[32];
#pragma unroll
        for (int c = 0; c < 32; c++) ov[c] = 0.0f;
        const float scale = 0.3535533905932738f;
#pragma unroll
        for (int hh = 0; hh < 4; hh++) {
            const int base = hh * 8;
            float mx = -1e30f;
            for (int kk = 0; kk < 64; kk++) {
                float s = 0.0f;
#pragma unroll
                for (int d = 0; d < 8; d++) s = fmaf(q[base + d], kbuf[kk * 33 + base + d], s);
                mx = fmaxf(mx, s * scale);
            }
            float sum = 0.0f;
            for (int kk = 0; kk < 64; kk++) {
                float s = 0.0f;
#pragma unroll
                for (int d = 0; d < 8; d++) s = fmaf(q[base + d], kbuf[kk * 33 + base + d], s);
                sum += __expf(s * scale - mx);
            }
            float inv = 1.0f / sum;
            for (int kk = 0; kk < 64; kk++) {
                float s = 0.0f;
#pragma unroll
                for (int d = 0; d < 8; d++) s = fmaf(q[base + d], kbuf[kk * 33 + base + d], s);
                float pw = __expf(s * scale - mx) * inv;
#pragma unroll
                for (int d = 0; d < 8; d++) ov[base + d] = fmaf(pw, vbuf[kk * 33 + base + d], ov[base + d]);
            }
        }

#pragma unroll
        for (int c = 0; c < 32; c++) {
            float s = s_projb[c];
#pragma unroll
            for (int u = 0; u < 32; u++) s = fmaf(ov[u], s_projw[u * 32 + c], s);
            xr[c] += s;
        }

        mu = 0.0f;
#pragma unroll
        for (int c = 0; c < 32; c++) mu += xr[c];
        mu *= 0.03125f;
        var = 0.0f;
#pragma unroll
        for (int c = 0; c < 32; c++) { float d = xr[c] - mu; var = fmaf(d, d, var); }
        var *= 0.03125f;
        rstd = rsqrtf(var + 1e-5f);
#pragma unroll
        for (int c = 0; c < 32; c++) hv[c] = (xr[c] - mu) * rstd * s_g2[c] + s_b2[c];

        float acc[32];
#pragma unroll
        for (int c = 0; c < 32; c++) acc[c] = 0.0f;
        for (int u = 0; u < 64; u++) {
            float a = s_fc1b[u];
#pragma unroll
            for (int c = 0; c < 32; c++) a = fmaf(hv[c], s_fc1w[c * 64 + u], a);
            float g = gelu_tanh(a);
#pragma unroll
            for (int c = 0; c < 32; c++) acc[c] = fmaf(g, s_fc2w[u * 32 + c], acc[c]);
        }
#pragma unroll
        for (int c = 0; c < 32; c++) xr[c] += acc[c] + s_fc2b[c];
    }

#pragma unroll
    for (int c = 0; c < 32; c++) out[c * THW + p] = vid[c * THW + p] + xr[c];
}

// ---------------------------------------------------------------------------
extern "C" void kernel_launch(void* const* d_in, const int* in_sizes, int n_in,
                              void* d_out, int out_size) {
    const float* vid    = (const float*)d_in[0];
    const float* conv_w = (const float*)d_in[1];
    const float* conv_b = (const float*)d_in[2];
    const float* ln1_g  = (const float*)d_in[3];
    const float* ln1_b  = (const float*)d_in[4];
    const float* qkv_w  = (const float*)d_in[5];
    const float* qkv_b  = (const float*)d_in[6];
    const float* proj_w = (const float*)d_in[7];
    const float* proj_b = (const float*)d_in[8];
    const float* ln2_g  = (const float*)d_in[9];
    const float* ln2_b  = (const float*)d_in[10];
    const float* fc1_w  = (const float*)d_in[11];
    const float* fc1_b  = (const float*)d_in[12];
    const float* fc2_w  = (const float*)d_in[13];
    const float* fc2_b  = (const float*)d_in[14];
    float* out = (float*)d_out;

    nl_stack_kernel<<<512, 128>>>(vid);
    wT_kernel<<<576, 128>>>(conv_w);
    conv_mma_kernel<<<1024, 128>>>(conv_b);

    const int smem_bytes = (8544 + 2 * 2 * 64 * 33) * (int)sizeof(float);  // 67968
    cudaFuncSetAttribute(xf_kernel, cudaFuncAttributeMaxDynamicSharedMemorySize, smem_bytes);
    xf_kernel<<<512, 128, smem_bytes>>>(vid, out,
                                        ln1_g, ln1_b, qkv_w, qkv_b, proj_w, proj_b,
                                        ln2_g, ln2_b, fc1_w, fc1_b, fc2_w, fc2_b);
}